// round 14
// baseline (speedup 1.0000x reference)
#include <cuda_runtime.h>
#include <math.h>

#define NB   8
#define NT   128
#define NS   400
#define NH   256
#define NVOC 50257
#define NBT  (NB * NT)
#define BMW  1572              // bitmap words per batch: ceil(50257/32)=1571, +1 pad (zeroed)
#define HSZ  1024              // dedup hash table slots (power of two)
#define N4   12865792u         // total float4s = NBT*NVOC/4 (exact)
#define ITER 4                 // float4s per thread in mix

// ---------------- scratch (__device__ globals; no allocation allowed) --------
__device__ float2   g_coeff[NBT];       // per (b,t): {p_gen, -(1-p)*lse}
__device__ float    g_corr[NBT * NS];   // per (b,t,head s): (1-p)*c_v  (heads only)
__device__ unsigned g_bm[NB * BMW];     // per-b bitmap of touched vocab ids
__device__ short    g_sidx[NB * NVOC];  // per-b map: vocab id -> head slot (valid where bit set)

// ---------------- block reductions: warp shuffle + 8-partial broadcast -------
__device__ __forceinline__ float block_sum_256(float v, float* red) {
    #pragma unroll
    for (int o = 16; o; o >>= 1) v += __shfl_xor_sync(0xffffffffu, v, o);
    if ((threadIdx.x & 31) == 0) red[threadIdx.x >> 5] = v;
    __syncthreads();
    float tot = red[0] + red[1] + red[2] + red[3] + red[4] + red[5] + red[6] + red[7];
    __syncthreads();
    return tot;
}
__device__ __forceinline__ float block_max_256(float v, float* red) {
    #pragma unroll
    for (int o = 16; o; o >>= 1) v = fmaxf(v, __shfl_xor_sync(0xffffffffu, v, o));
    if ((threadIdx.x & 31) == 0) red[threadIdx.x >> 5] = v;
    __syncthreads();
    float m = fmaxf(fmaxf(fmaxf(red[0], red[1]), fmaxf(red[2], red[3])),
                    fmaxf(fmaxf(red[4], red[5]), fmaxf(red[6], red[7])));
    __syncthreads();
    return m;
}

// ---------------- kernel 1: fused dedup + p_gen + grouped-sum + lse ----------
__global__ __launch_bounds__(256)
void rowstats_kernel(const int*   __restrict__ tokens,
                     const float* __restrict__ ctx,
                     const float* __restrict__ din,
                     const float* __restrict__ dout,
                     const float* __restrict__ attn,
                     const float* __restrict__ Wc, const float* __restrict__ bc,
                     const float* __restrict__ Wo, const float* __restrict__ bo,
                     const float* __restrict__ Wi, const float* __restrict__ bi) {
    const int bt  = blockIdx.x;
    const int b   = bt >> 7;            // bt / NT
    const int tid = threadIdx.x;

    __shared__ float red[8];
    __shared__ float c_sm[NS];
    __shared__ int   hkey[HSZ];
    __shared__ int   hrep[HSZ];
    __shared__ int   cnt;

    #pragma unroll
    for (int i = tid; i < HSZ; i += 256) { hkey[i] = -1; hrep[i] = 0x7fffffff; }
    c_sm[tid] = 0.0f;
    if (tid < NS - 256) c_sm[tid + 256] = 0.0f;
    if (tid == 0) cnt = 0;
    __syncthreads();

    // --- build: insert this batch's tokens (slots tid and tid+256) ---
    const int tok0 = tokens[b * NS + tid];
    int tok1 = -1;
    {
        unsigned h = ((unsigned)tok0 * 2654435761u) & (HSZ - 1u);
        for (;;) {
            const int old = atomicCAS(&hkey[h], -1, tok0);
            if (old == -1 || old == tok0) break;
            h = (h + 1u) & (HSZ - 1u);
        }
        atomicMin(&hrep[h], tid);
    }
    if (tid < NS - 256) {
        tok1 = tokens[b * NS + tid + 256];
        unsigned h = ((unsigned)tok1 * 2654435761u) & (HSZ - 1u);
        for (;;) {
            const int old = atomicCAS(&hkey[h], -1, tok1);
            if (old == -1 || old == tok1) break;
            h = (h + 1u) & (HSZ - 1u);
        }
        atomicMin(&hrep[h], tid + 256);
    }

    // --- p_gen partial while the table settles ---
    const int base = bt * NH + tid;
    float partial = ctx[base]  * Wc[tid]
                  + dout[base] * Wo[tid]
                  + din[base]  * Wi[tid];
    __syncthreads();

    // --- probe: canonical head per slot (plain reads; table is final) ---
    unsigned hh = ((unsigned)tok0 * 2654435761u) & (HSZ - 1u);
    while (hkey[hh] != tok0) hh = (hh + 1u) & (HSZ - 1u);
    const int h0 = hrep[hh];
    int h1 = -1;
    if (tid < NS - 256) {
        unsigned h = ((unsigned)tok1 * 2654435761u) & (HSZ - 1u);
        while (hkey[h] != tok1) h = (h + 1u) & (HSZ - 1u);
        h1 = hrep[h];
    }

    const float z = block_sum_256(partial, red) + bc[0] + bo[0] + bi[0];
    const float p = 1.0f / (1.0f + expf(-z));
    const float q = 1.0f - p;

    // --- group attn values by canonical head ---
    atomicAdd(&c_sm[h0], attn[bt * NS + tid]);
    if (tid < NS - 256) atomicAdd(&c_sm[h1], attn[bt * NS + tid + 256]);
    __syncthreads();

    const bool head0 = (h0 == tid);
    const bool head1 = (h1 == tid + 256);
    const float c0 = head0 ? c_sm[tid]       : 0.0f;
    const float c1 = head1 ? c_sm[tid + 256] : 0.0f;
    if (head0) atomicAdd(&cnt, 1);
    if (head1) atomicAdd(&cnt, 1);

    // --- max over row (implicit zeros make 0 a valid floor; c >= 0 anyway) ---
    float m = 0.0f;
    if (head0) m = fmaxf(m, c0);
    if (head1) m = fmaxf(m, c1);
    m = block_max_256(m, red);

    // --- sumexp over heads + (V - n) zeros ---
    float se = 0.0f;
    if (head0) se += expf(c0 - m);
    if (head1) se += expf(c1 - m);
    se = block_sum_256(se, red);   // cnt's atomicAdds are pre-barrier: visible after

    if (tid == 0) {
        const float total = se + (float)(NVOC - cnt) * expf(-m);
        const float lse = m + logf(total);
        g_coeff[bt] = make_float2(p, -q * lse);
    }

    // --- correction values for fused-mix lookup ---
    if (head0) g_corr[bt * NS + tid]       = q * c0;
    if (head1) g_corr[bt * NS + tid + 256] = q * c1;

    // --- designated block per batch publishes bitmap + slot map ---
    if ((bt & (NT - 1)) == 0) {
        #pragma unroll
        for (int i = tid; i < BMW; i += 256) g_bm[b * BMW + i] = 0u;
        __syncthreads();
        if (head0) {
            atomicOr(&g_bm[b * BMW + ((unsigned)tok0 >> 5)], 1u << (tok0 & 31));
            g_sidx[b * NVOC + tok0] = (short)tid;
        }
        if (head1) {
            atomicOr(&g_bm[b * BMW + ((unsigned)tok1 >> 5)], 1u << (tok1 & 31));
            g_sidx[b * NVOC + tok1] = (short)(tid + 256);
        }
    }
}

// ---------------- kernel 2: streaming affine mix, MLP-batched ----------------
// Block tile = ITER*256 float4s; each thread owns ITER float4s strided by 256.
// Phase 1 issues ALL loads (vocab + coeff + bitmap pair) before any compute,
// giving ~16 outstanding loads per thread; phase 2 does FMAs + streaming store.
__global__ __launch_bounds__(256)
void mix_kernel(const float4* __restrict__ vocab, float4* __restrict__ out) {
    const unsigned t0 = blockIdx.x * (256u * ITER) + threadIdx.x;

    float4   v[ITER];
    float2   cf[ITER];
    unsigned bits[ITER];
    unsigned bt[ITER], rem[ITER];
    bool     ok[ITER], simple[ITER];

    // ---- phase 1: front-batch every load ----
    #pragma unroll
    for (int k = 0; k < ITER; ++k) {
        const unsigned i4 = t0 + k * 256u;
        ok[k] = (i4 < N4);
        const unsigned base = i4 * 4u;
        bt[k]  = base / (unsigned)NVOC;
        rem[k] = base - bt[k] * (unsigned)NVOC;
        simple[k] = (rem[k] <= (unsigned)(NVOC - 4));
        if (ok[k]) {
            v[k]  = __ldcs(&vocab[i4]);
            cf[k] = g_coeff[bt[k]];
            const unsigned* __restrict__ bm = g_bm + (bt[k] >> 7) * BMW;
            const unsigned w0 = rem[k] >> 5;
            // pad word (index 1571) is zeroed, so the pair load is always safe
            bits[k] = __funnelshift_r(bm[w0], bm[w0 + 1], rem[k] & 31u) & 15u;
        }
    }

    // ---- phase 2: compute + store ----
    #pragma unroll
    for (int k = 0; k < ITER; ++k) {
        if (!ok[k]) continue;
        const unsigned i4 = t0 + k * 256u;
        float4 o;
        if (simple[k]) {
            o.x = fmaf(v[k].x, cf[k].x, cf[k].y);
            o.y = fmaf(v[k].y, cf[k].x, cf[k].y);
            o.z = fmaf(v[k].z, cf[k].x, cf[k].y);
            o.w = fmaf(v[k].w, cf[k].x, cf[k].y);
            if (bits[k]) {   // rare (~0.8% of float4s)
                const unsigned b = bt[k] >> 7;
                const short* __restrict__ sx   = g_sidx + b * NVOC;
                const float* __restrict__ corr = g_corr + bt[k] * NS;
                if (bits[k] & 1u) o.x += corr[sx[rem[k] + 0u]];
                if (bits[k] & 2u) o.y += corr[sx[rem[k] + 1u]];
                if (bits[k] & 4u) o.z += corr[sx[rem[k] + 2u]];
                if (bits[k] & 8u) o.w += corr[sx[rem[k] + 3u]];
            }
        } else {
            // straddles a row boundary (V odd): fully general path (rare)
            const unsigned base = i4 * 4u;
            float vv[4] = {v[k].x, v[k].y, v[k].z, v[k].w};
            float oo[4];
            #pragma unroll
            for (int i = 0; i < 4; ++i) {
                const unsigned g   = base + (unsigned)i;
                const unsigned bte = g / (unsigned)NVOC;
                const unsigned r   = g - bte * (unsigned)NVOC;
                const unsigned b   = bte >> 7;
                const float2 c = g_coeff[bte];
                float val = fmaf(vv[i], c.x, c.y);
                if ((g_bm[b * BMW + (r >> 5)] >> (r & 31u)) & 1u)
                    val += g_corr[bte * NS + g_sidx[b * NVOC + r]];
                oo[i] = val;
            }
            o.x = oo[0]; o.y = oo[1]; o.z = oo[2]; o.w = oo[3];
        }
        __stcs(&out[i4], o);
    }
}

// ---------------- launch ------------------------------------------------------
extern "C" void kernel_launch(void* const* d_in, const int* in_sizes, int n_in,
                              void* d_out, int out_size) {
    const int*   tokens = (const int*)  d_in[0];   // [B, S]
    const float* ctx    = (const float*)d_in[1];   // [B, T, H]
    const float* din    = (const float*)d_in[2];   // [B, T, H]
    const float* dout   = (const float*)d_in[3];   // [B, T, H]
    const float* vocab  = (const float*)d_in[4];   // [B, T, V]
    const float* attn   = (const float*)d_in[5];   // [B, T, S]
    // d_in[6] = encoder_outputs (unused by reference)
    const float* Wc = (const float*)d_in[7];
    const float* bc = (const float*)d_in[8];
    const float* Wo = (const float*)d_in[9];
    const float* bo = (const float*)d_in[10];
    const float* Wi = (const float*)d_in[11];
    const float* bi = (const float*)d_in[12];
    float* out = (float*)d_out;

    rowstats_kernel<<<NBT, 256>>>(tokens, ctx, din, dout, attn,
                                  Wc, bc, Wo, bo, Wi, bi);
    const unsigned nblk = (N4 + 256u * ITER - 1u) / (256u * ITER);   // 12565
    mix_kernel<<<nblk, 256>>>((const float4*)vocab, (float4*)out);
}

// round 15
// speedup vs baseline: 1.0340x; 1.0340x over previous
#include <cuda_runtime.h>
#include <math.h>
#include <stdint.h>

#define NB   8
#define NT   128
#define NS   400
#define NH   256
#define NVOC 50257
#define NBT  (NB * NT)
#define BMW  1572              // bitmap words per batch: ceil(50257/32)=1571, +1 pad (zeroed)
#define HSZ  1024              // dedup hash table slots (power of two)
#define NTOT 51463168u         // total floats = NBT*NVOC
#define TILE_F4 1024u          // float4s per tile (16 KB)
#define NTILE 12565u           // ceil(NTOT/4096)

// ---------------- scratch (__device__ globals; no allocation allowed) --------
__device__ float2   g_coeff[NBT];       // per (b,t): {p_gen, -(1-p)*lse}
__device__ float    g_corr[NBT * NS];   // per (b,t,head s): (1-p)*c_v  (heads only)
__device__ unsigned g_bm[NB * BMW];     // per-b bitmap of touched vocab ids
__device__ short    g_sidx[NB * NVOC];  // per-b map: vocab id -> head slot (valid where bit set)

// ---------------- block reductions: warp shuffle + 8-partial broadcast -------
__device__ __forceinline__ float block_sum_256(float v, float* red) {
    #pragma unroll
    for (int o = 16; o; o >>= 1) v += __shfl_xor_sync(0xffffffffu, v, o);
    if ((threadIdx.x & 31) == 0) red[threadIdx.x >> 5] = v;
    __syncthreads();
    float tot = red[0] + red[1] + red[2] + red[3] + red[4] + red[5] + red[6] + red[7];
    __syncthreads();
    return tot;
}
__device__ __forceinline__ float block_max_256(float v, float* red) {
    #pragma unroll
    for (int o = 16; o; o >>= 1) v = fmaxf(v, __shfl_xor_sync(0xffffffffu, v, o));
    if ((threadIdx.x & 31) == 0) red[threadIdx.x >> 5] = v;
    __syncthreads();
    float m = fmaxf(fmaxf(fmaxf(red[0], red[1]), fmaxf(red[2], red[3])),
                    fmaxf(fmaxf(red[4], red[5]), fmaxf(red[6], red[7])));
    __syncthreads();
    return m;
}

// ---------------- kernel 1: fused dedup + p_gen + grouped-sum + lse ----------
__global__ __launch_bounds__(256)
void rowstats_kernel(const int*   __restrict__ tokens,
                     const float* __restrict__ ctx,
                     const float* __restrict__ din,
                     const float* __restrict__ dout,
                     const float* __restrict__ attn,
                     const float* __restrict__ Wc, const float* __restrict__ bc,
                     const float* __restrict__ Wo, const float* __restrict__ bo,
                     const float* __restrict__ Wi, const float* __restrict__ bi) {
    const int bt  = blockIdx.x;
    const int b   = bt >> 7;            // bt / NT
    const int tid = threadIdx.x;

    __shared__ float red[8];
    __shared__ float c_sm[NS];
    __shared__ int   hkey[HSZ];
    __shared__ int   hrep[HSZ];
    __shared__ int   cnt;

    #pragma unroll
    for (int i = tid; i < HSZ; i += 256) { hkey[i] = -1; hrep[i] = 0x7fffffff; }
    c_sm[tid] = 0.0f;
    if (tid < NS - 256) c_sm[tid + 256] = 0.0f;
    if (tid == 0) cnt = 0;
    __syncthreads();

    // --- build: insert this batch's tokens (slots tid and tid+256) ---
    const int tok0 = tokens[b * NS + tid];
    int tok1 = -1;
    {
        unsigned h = ((unsigned)tok0 * 2654435761u) & (HSZ - 1u);
        for (;;) {
            const int old = atomicCAS(&hkey[h], -1, tok0);
            if (old == -1 || old == tok0) break;
            h = (h + 1u) & (HSZ - 1u);
        }
        atomicMin(&hrep[h], tid);
    }
    if (tid < NS - 256) {
        tok1 = tokens[b * NS + tid + 256];
        unsigned h = ((unsigned)tok1 * 2654435761u) & (HSZ - 1u);
        for (;;) {
            const int old = atomicCAS(&hkey[h], -1, tok1);
            if (old == -1 || old == tok1) break;
            h = (h + 1u) & (HSZ - 1u);
        }
        atomicMin(&hrep[h], tid + 256);
    }

    // --- p_gen partial while the table settles ---
    const int base = bt * NH + tid;
    float partial = ctx[base]  * Wc[tid]
                  + dout[base] * Wo[tid]
                  + din[base]  * Wi[tid];
    __syncthreads();

    // --- probe: canonical head per slot (plain reads; table is final) ---
    unsigned hh = ((unsigned)tok0 * 2654435761u) & (HSZ - 1u);
    while (hkey[hh] != tok0) hh = (hh + 1u) & (HSZ - 1u);
    const int h0 = hrep[hh];
    int h1 = -1;
    if (tid < NS - 256) {
        unsigned h = ((unsigned)tok1 * 2654435761u) & (HSZ - 1u);
        while (hkey[h] != tok1) h = (h + 1u) & (HSZ - 1u);
        h1 = hrep[h];
    }

    const float z = block_sum_256(partial, red) + bc[0] + bo[0] + bi[0];
    const float p = 1.0f / (1.0f + expf(-z));
    const float q = 1.0f - p;

    // --- group attn values by canonical head ---
    atomicAdd(&c_sm[h0], attn[bt * NS + tid]);
    if (tid < NS - 256) atomicAdd(&c_sm[h1], attn[bt * NS + tid + 256]);
    __syncthreads();

    const bool head0 = (h0 == tid);
    const bool head1 = (h1 == tid + 256);
    const float c0 = head0 ? c_sm[tid]       : 0.0f;
    const float c1 = head1 ? c_sm[tid + 256] : 0.0f;
    if (head0) atomicAdd(&cnt, 1);
    if (head1) atomicAdd(&cnt, 1);

    // --- max over row (implicit zeros make 0 a valid floor; c >= 0 anyway) ---
    float m = 0.0f;
    if (head0) m = fmaxf(m, c0);
    if (head1) m = fmaxf(m, c1);
    m = block_max_256(m, red);

    // --- sumexp over heads + (V - n) zeros ---
    float se = 0.0f;
    if (head0) se += expf(c0 - m);
    if (head1) se += expf(c1 - m);
    se = block_sum_256(se, red);   // cnt's atomicAdds are pre-barrier: visible after

    if (tid == 0) {
        const float total = se + (float)(NVOC - cnt) * expf(-m);
        const float lse = m + logf(total);
        g_coeff[bt] = make_float2(p, -q * lse);
    }

    // --- correction values for fused-mix lookup ---
    if (head0) g_corr[bt * NS + tid]       = q * c0;
    if (head1) g_corr[bt * NS + tid + 256] = q * c1;

    // --- designated block per batch publishes bitmap + slot map ---
    if ((bt & (NT - 1)) == 0) {
        #pragma unroll
        for (int i = tid; i < BMW; i += 256) g_bm[b * BMW + i] = 0u;
        __syncthreads();
        if (head0) {
            atomicOr(&g_bm[b * BMW + ((unsigned)tok0 >> 5)], 1u << (tok0 & 31));
            g_sidx[b * NVOC + tok0] = (short)tid;
        }
        if (head1) {
            atomicOr(&g_bm[b * BMW + ((unsigned)tok1 >> 5)], 1u << (tok1 & 31));
            g_sidx[b * NVOC + tok1] = (short)(tid + 256);
        }
    }
}

// ---------------- kernel 2: TMA-tiled streaming affine mix -------------------
// One 16 KB tile per block: cp.async.bulk g->smem, compute in place from smem
// (LDS/STS instead of LDG.128/STG.128 — removes the LSU issue-cost wall),
// cp.async.bulk smem->g. 8 blocks/SM stagger their TMA phases to hide latency.
__global__ __launch_bounds__(256)
void mix_kernel(const float* __restrict__ vocab, float* __restrict__ out) {
    __shared__ __align__(128) float4 s4[TILE_F4];     // 16 KB tile, in-place
    __shared__ __align__(8) uint64_t mbar;

    const unsigned tile   = blockIdx.x;
    const unsigned base_f = tile * (TILE_F4 * 4u);              // first float
    const unsigned nf     = (NTOT - base_f < TILE_F4 * 4u) ? (NTOT - base_f)
                                                           : (TILE_F4 * 4u);
    const unsigned bytes  = nf * 4u;
    const unsigned tid    = threadIdx.x;

    const unsigned smem_data = (unsigned)__cvta_generic_to_shared(s4);
    const unsigned smem_mbar = (unsigned)__cvta_generic_to_shared(&mbar);

    if (tid == 0) {
        asm volatile("mbarrier.init.shared.b64 [%0], %1;"
                     :: "r"(smem_mbar), "r"(1u) : "memory");
    }
    __syncthreads();

    if (tid == 0) {
        asm volatile("mbarrier.arrive.expect_tx.shared.b64 _, [%0], %1;"
                     :: "r"(smem_mbar), "r"(bytes) : "memory");
        asm volatile("cp.async.bulk.shared::cluster.global.mbarrier::complete_tx::bytes "
                     "[%0], [%1], %2, [%3];"
                     :: "r"(smem_data), "l"(vocab + base_f), "r"(bytes),
                        "r"(smem_mbar) : "memory");
    }

    // wait for TMA fill (parity 0, acquire)
    {
        unsigned done;
        asm volatile(
            "{\n\t.reg .pred p;\n\t"
            "mbarrier.try_wait.parity.acquire.cta.shared::cta.b64 p, [%1], %2;\n\t"
            "selp.b32 %0, 1, 0, p;\n\t}"
            : "=r"(done) : "r"(smem_mbar), "r"(0u) : "memory");
        if (!done) {
            asm volatile(
                "{\n\t.reg .pred P1;\n\t"
                "WL_%=:\n\t"
                "mbarrier.try_wait.parity.acquire.cta.shared::cta.b64 P1, [%0], %1, 0x989680;\n\t"
                "@P1 bra.uni WD_%=;\n\t"
                "bra.uni WL_%=;\n\t"
                "WD_%=:\n\t}"
                :: "r"(smem_mbar), "r"(0u) : "memory");
        }
    }

    // ---- compute in place: 4 float4s per thread ----
    #pragma unroll
    for (int k = 0; k < 4; ++k) {
        const unsigned i4l = tid + k * 256u;
        if (i4l * 16u >= bytes) break;                 // partial last tile only
        const float4 v = s4[i4l];
        const unsigned e   = base_f + i4l * 4u;        // global element index
        const unsigned bt0 = e / (unsigned)NVOC;
        const unsigned rem = e - bt0 * (unsigned)NVOC;

        float4 o;
        if (rem <= (unsigned)(NVOC - 4)) {
            const float2 cf = g_coeff[bt0];
            o.x = fmaf(v.x, cf.x, cf.y);
            o.y = fmaf(v.y, cf.x, cf.y);
            o.z = fmaf(v.z, cf.x, cf.y);
            o.w = fmaf(v.w, cf.x, cf.y);

            const unsigned b = bt0 >> 7;
            const unsigned* __restrict__ bm = g_bm + b * BMW;
            const unsigned w0 = rem >> 5;
            const unsigned bits =
                __funnelshift_r(bm[w0], bm[w0 + 1], rem & 31u) & 15u;
            if (bits) {   // rare (~0.8% of float4s)
                const short* __restrict__ sx   = g_sidx + b * NVOC;
                const float* __restrict__ corr = g_corr + bt0 * NS;
                if (bits & 1u) o.x += corr[sx[rem + 0u]];
                if (bits & 2u) o.y += corr[sx[rem + 1u]];
                if (bits & 4u) o.z += corr[sx[rem + 2u]];
                if (bits & 8u) o.w += corr[sx[rem + 3u]];
            }
        } else {
            // float4 straddles a row boundary (V odd): general path (rare)
            float vv[4] = {v.x, v.y, v.z, v.w};
            float oo[4];
            #pragma unroll
            for (int i = 0; i < 4; ++i) {
                const unsigned g   = e + (unsigned)i;
                const unsigned bte = g / (unsigned)NVOC;
                const unsigned r   = g - bte * (unsigned)NVOC;
                const unsigned b   = bte >> 7;
                const float2 c = g_coeff[bte];
                float val = fmaf(vv[i], c.x, c.y);
                if ((g_bm[b * BMW + (r >> 5)] >> (r & 31u)) & 1u)
                    val += g_corr[bte * NS + g_sidx[b * NVOC + r]];
                oo[i] = val;
            }
            o.x = oo[0]; o.y = oo[1]; o.z = oo[2]; o.w = oo[3];
        }
        s4[i4l] = o;
    }
    __syncthreads();

    // ---- bulk store smem -> global ----
    if (tid == 0) {
        asm volatile("fence.proxy.async.shared::cta;" ::: "memory");
        asm volatile("cp.async.bulk.global.shared::cta.bulk_group [%0], [%1], %2;"
                     :: "l"(out + base_f), "r"(smem_data), "r"(bytes) : "memory");
        asm volatile("cp.async.bulk.commit_group;" ::: "memory");
        asm volatile("cp.async.bulk.wait_group 0;" ::: "memory");
    }
}

// ---------------- launch ------------------------------------------------------
extern "C" void kernel_launch(void* const* d_in, const int* in_sizes, int n_in,
                              void* d_out, int out_size) {
    const int*   tokens = (const int*)  d_in[0];   // [B, S]
    const float* ctx    = (const float*)d_in[1];   // [B, T, H]
    const float* din    = (const float*)d_in[2];   // [B, T, H]
    const float* dout   = (const float*)d_in[3];   // [B, T, H]
    const float* vocab  = (const float*)d_in[4];   // [B, T, V]
    const float* attn   = (const float*)d_in[5];   // [B, T, S]
    // d_in[6] = encoder_outputs (unused by reference)
    const float* Wc = (const float*)d_in[7];
    const float* bc = (const float*)d_in[8];
    const float* Wo = (const float*)d_in[9];
    const float* bo = (const float*)d_in[10];
    const float* Wi = (const float*)d_in[11];
    const float* bi = (const float*)d_in[12];
    float* out = (float*)d_out;

    rowstats_kernel<<<NBT, 256>>>(tokens, ctx, din, dout, attn,
                                  Wc, bc, Wo, bo, Wi, bi);
    mix_kernel<<<NTILE, 256>>>(vocab, out);
}